// round 14
// baseline (speedup 1.0000x reference)
#include <cuda_runtime.h>

#define BB 128
#define CIN 16
#define COUT 32
#define HH 32
#define WW 32
#define HOUT 30
#define WOUT 30
#define PP 900
#define KC 144            // CIN * 9
#define NELEM (BB*COUT*PP)   // 3686400
#define BO 4096           // BB*COUT
#define FIXCAP (1<<20)
#define MARGIN_TAU 2e-3f

// ---------------- scratch (static __device__, no allocation) ----------------
__device__ float  g_fft[CIN*HH*WW*BB];   // [c][y][x][b]
__device__ float  g_spkt[PP*BO];         // [p][j][b]
__device__ float  g_wtt[PP*KC*COUT];     // [p][kc][o]
__device__ float  g_conv[PP*BO];         // [p][b*32+o]
__device__ float  g_rec[PP*BO];          // [p][b*32+o]
__device__ double g_part[PP*64];         // [p][ sum(32) | sumsq(32) ]
__device__ float  g_mean[COUT];
__device__ float  g_rstd[COUT];
__device__ float  g_alpha[COUT*PP];
__device__ float  g_rho[COUT*PP];
__device__ float  g_eta[COUT*PP];
__device__ int    g_fix_cnt;
__device__ int    g_fix_list[FIXCAP];

union F4U2 { float4 f4; unsigned long long u2[2]; float f[4]; };

__device__ __forceinline__ unsigned long long ffma2(
    unsigned long long a, unsigned long long b, unsigned long long c) {
    unsigned long long d;
    asm("fma.rn.f32x2 %0, %1, %2, %3;" : "=l"(d) : "l"(a), "l"(b), "l"(c));
    return d;
}

// ---------------- kernel 1a: transpose ff [128][16384] -> [16384][128] ------
__global__ void k_transpose_ff(const float* __restrict__ ff) {
    __shared__ float t[32][33];
    int x  = blockIdx.x*32 + threadIdx.x;   // chw
    int y0 = blockIdx.y*32;                 // b
#pragma unroll
    for (int j = 0; j < 32; j += 8)
        t[threadIdx.y+j][threadIdx.x] = ff[(size_t)(y0+threadIdx.y+j)*16384 + x];
    __syncthreads();
    int xo  = blockIdx.y*32 + threadIdx.x;  // b
    int yo0 = blockIdx.x*32;
#pragma unroll
    for (int j = 0; j < 32; j += 8)
        g_fft[(size_t)(yo0+threadIdx.y+j)*128 + xo] = t[threadIdx.x][threadIdx.y+j];
}

// ---------------- kernel 1b: transpose spk [b][j][p] -> [p][j][b] -----------
__global__ void k_transpose_spk(const float* __restrict__ spk) {
    __shared__ float t[32][33];
    int jz = blockIdx.z;                    // 0..31
    int x  = blockIdx.x*32 + threadIdx.x;   // p
    int y0 = blockIdx.y*32;                 // b
#pragma unroll
    for (int j = 0; j < 32; j += 8) {
        int b = y0 + threadIdx.y + j;
        if (x < PP)
            t[threadIdx.y+j][threadIdx.x] = spk[((size_t)b*32 + jz)*PP + x];
    }
    __syncthreads();
    int bo = blockIdx.y*32 + threadIdx.x;   // b
#pragma unroll
    for (int j = 0; j < 32; j += 8) {
        int p = blockIdx.x*32 + threadIdx.y + j;
        if (p < PP)
            g_spkt[(size_t)p*BO + jz*128 + bo] = t[threadIdx.x][threadIdx.y+j];
    }
}

// ---------------- kernel 1c: weight [o][c][p][k] -> [p][c*9+k][o] -----------
__global__ void k_transform_w(const float* __restrict__ wt) {
    __shared__ float s[32*145];             // [o][r], r < 144 (16 p x 9 k)
    int c  = blockIdx.y;                    // 0..15
    int p0 = blockIdx.x*16;                 // 57 blocks (912 >= 900)
    int tid = threadIdx.x;
    int o = tid >> 3, lane = tid & 7;
    int rmax = (PP - p0)*9; if (rmax > 144) rmax = 144;
    const float* src = wt + (((size_t)o*CIN + c)*PP + p0)*9;
#pragma unroll
    for (int j = 0; j < 18; j++) {
        int r = lane + 8*j;
        if (r < rmax) s[o*145 + r] = src[r];
    }
    __syncthreads();
#pragma unroll
    for (int i = 0; i < 18; i++) {
        int idx = tid + 256*i;              // 4608 = 16*9*32
        int o2 = idx & 31, r = idx >> 5;
        int pl = r / 9, k = r - pl*9;
        if (p0 + pl < PP)
            g_wtt[((size_t)(p0+pl)*KC + c*9 + k)*32 + o2] = s[o2*145 + r];
    }
}

// ---------------- kernel 1d: precompute alpha/rho/eta per (o,p) -------------
__global__ void k_taus(const float* __restrict__ tau_m,
                       const float* __restrict__ tau_adp,
                       const float* __restrict__ tau_a) {
    int i = blockIdx.x*256 + threadIdx.x;
    if (i < COUT*PP) {
        g_alpha[i] = expf(__fdiv_rn(-0.5f, tau_m[i]));
        g_rho[i]   = expf(__fdiv_rn(-0.5f, tau_adp[i]));
        g_eta[i]   = expf(__fdiv_rn(-0.5f, tau_a[i]));
    }
}

// ---------------- kernel 2: per-location conv + rec GEMMs -------------------
// o=8 per warp, k-half split; patch via LDG (compile-time offsets).
// Partials round-trip through smem (no 'own' registers) -> 51-reg cap,
// 5 CTAs/SM (smem 5 x 41472 = 207KB).
__global__ __launch_bounds__(256, 5) void k_conv_rec(
    const float* __restrict__ lr, const float* __restrict__ bias) {
    extern __shared__ float sm[];
    float4* sw4     = (float4*)sm;          // [k2*32+o] = (we,we,wo,wo), 2304
    float*  s_lr    = sm + 9216;            // [j*36 + o], 1152 floats
    float*  s_comb  = sm;                   // reuse: [e*256 + tid], 8192
    float*  s_stage = sm;                   // reuse: 4224 floats
    float4* sl4     = (float4*)s_lr;

    int p = blockIdx.x;
    int h = p / 30, w = p - h*30;
    int tid = threadIdx.x;
    int warp = tid >> 5, bi = tid & 31;
    int kh = warp & 1;                      // k-half
    int og = warp >> 1;                     // o octet (0..3)

    for (int idx = tid; idx < 2304; idx += 256) {
        int k2 = idx >> 5, o = idx & 31;
        float we = g_wtt[((size_t)p*KC + 2*k2    )*32 + o];
        float wo = g_wtt[((size_t)p*KC + 2*k2 + 1)*32 + o];
        sw4[idx] = make_float4(we, we, wo, wo);
    }
    for (int idx = tid; idx < 1024; idx += 256)
        s_lr[(idx & 31)*36 + (idx >> 5)] = lr[(size_t)p*1024 + idx];
    __syncthreads();

    const float4* pbase = ((const float4*)g_fft) + ((size_t)h*32 + w)*32 + bi
                          + (size_t)kh*8*32768;
    const float4* wbase = sw4 + kh*36*32 + og*8;
    unsigned long long acc2[8][2] = {};
#pragma unroll
    for (int i = 0; i < 36; i++) {
        const int ke = 2*i,   ko = ke + 1;
        const int ce = ke/9,  re = ke - ce*9, ye = re/3, xe = re - ye*3;
        const int co = ko/9,  ro = ko - co*9, yo = ro/3, xo = ro - yo*3;
        F4U2 pe, po;
        pe.f4 = __ldg(pbase + ce*32768 + ye*1024 + xe*32);
        po.f4 = __ldg(pbase + co*32768 + yo*1024 + xo*32);
#pragma unroll
        for (int j = 0; j < 8; j++) {
            F4U2 wv; wv.f4 = wbase[i*32 + j];
            acc2[j][0] = ffma2(pe.u2[0], wv.u2[0], acc2[j][0]);
            acc2[j][1] = ffma2(pe.u2[1], wv.u2[0], acc2[j][1]);
            acc2[j][0] = ffma2(po.u2[0], wv.u2[1], acc2[j][0]);
            acc2[j][1] = ffma2(po.u2[1], wv.u2[1], acc2[j][1]);
        }
    }
    __syncthreads();                // all warps done reading sw4
    // publish ALL partials to smem (acc2 regs die here)
#pragma unroll
    for (int j = 0; j < 8; j++) {
        F4U2 u; u.u2[0] = acc2[j][0]; u.u2[1] = acc2[j][1];
#pragma unroll
        for (int i = 0; i < 4; i++)
            s_comb[(j*4 + i)*256 + tid] = u.f[i];
    }
    __syncthreads();

    if (kh == 0) {
        // combine halves + bias, BN partials in two groups of 4 (reg relief)
#pragma unroll
        for (int jg = 0; jg < 2; jg++) {
            float acc[4][4];
            double ps[4], pq[4];
#pragma unroll
            for (int j = 0; j < 4; j++) {
                int jj = jg*4 + j;
                float bv = bias[(og*8 + jj)*PP + p];
#pragma unroll
                for (int i = 0; i < 4; i++) {
                    int e = (jj*4 + i)*256 + tid;
                    acc[j][i] = __fadd_rn(
                        __fadd_rn(s_comb[e], s_comb[e + 32]), bv);
                }
            }
#pragma unroll
            for (int j = 0; j < 4; j++) {
                double a0 = acc[j][0], a1 = acc[j][1], a2 = acc[j][2], a3 = acc[j][3];
                ps[j] = (a0 + a1) + (a2 + a3);
                pq[j] = (a0*a0 + a1*a1) + (a2*a2 + a3*a3);
            }
#pragma unroll
            for (int off = 16; off > 0; off >>= 1) {
#pragma unroll
                for (int j = 0; j < 4; j++) {
                    ps[j] += __shfl_down_sync(0xffffffffu, ps[j], off);
                    pq[j] += __shfl_down_sync(0xffffffffu, pq[j], off);
                }
            }
            if (bi == 0) {
#pragma unroll
                for (int j = 0; j < 4; j++) {
                    g_part[p*64 + og*8 + jg*4 + j]      = ps[j];
                    g_part[p*64 + 32 + og*8 + jg*4 + j] = pq[j];
                }
            }
            // hold combined values in s_comb's own-half slot for staging
#pragma unroll
            for (int j = 0; j < 4; j++)
#pragma unroll
                for (int i = 0; i < 4; i++)
                    s_comb[((jg*4 + j)*4 + i)*256 + tid] = acc[j][i];
        }
    }
    __syncthreads();
    // stage combined conv values -> coalesced global write
    // s_comb[e*256 + tid(kh=0 half)] holds out(o=og*8+j, b=4bi+i)
    {
        // rebuild stage tile [b][o] with stride-33 from s_comb
        // only kh==0 threads' slots are valid: tid with warp even
        // each thread (any) copies from s_comb using mapped index
        for (int idx = tid; idx < 4096; idx += 256) {
            int b4 = idx >> 5;              // 0..127  (b index)
            int o  = idx & 31;              // o index
            int bi2 = b4 >> 2, i2 = b4 & 3;
            int ogg = o >> 3, j2 = o & 7;
            int src_tid = (ogg*2)*32 + bi2; // kh=0 warp for this octet
            float v = s_comb[(j2*4 + i2)*256 + src_tid];
            g_conv[(size_t)p*BO + idx] = v;
        }
    }

    // ---- rec GEMM (f32, spk via LDG) ----
    int oi = warp;
    float racc[4][4];
#pragma unroll
    for (int j = 0; j < 4; j++)
#pragma unroll
        for (int i = 0; i < 4; i++) racc[j][i] = 0.f;
    const float4* skb = ((const float4*)g_spkt) + (size_t)p*1024 + bi;
#pragma unroll 8
    for (int jj = 0; jj < 32; jj++) {
        float4 pv = __ldg(skb + jj*32);
        float4 lv = sl4[jj*9 + oi];
        racc[0][0] += pv.x*lv.x; racc[0][1] += pv.y*lv.x; racc[0][2] += pv.z*lv.x; racc[0][3] += pv.w*lv.x;
        racc[1][0] += pv.x*lv.y; racc[1][1] += pv.y*lv.y; racc[1][2] += pv.z*lv.y; racc[1][3] += pv.w*lv.y;
        racc[2][0] += pv.x*lv.z; racc[2][1] += pv.y*lv.z; racc[2][2] += pv.z*lv.z; racc[2][3] += pv.w*lv.z;
        racc[3][0] += pv.x*lv.w; racc[3][1] += pv.y*lv.w; racc[3][2] += pv.z*lv.w; racc[3][3] += pv.w*lv.w;
    }
    __syncthreads();                // conv writes done reading s_comb
#pragma unroll
    for (int i = 0; i < 4; i++)
#pragma unroll
        for (int j = 0; j < 4; j++)
            s_stage[(4*bi + i)*33 + 4*oi + j] = racc[j][i];
    __syncthreads();
    for (int idx = tid; idx < 4096; idx += 256)
        g_rec[(size_t)p*BO + idx] = s_stage[(idx >> 5)*33 + (idx & 31)];
}

// ---------------- kernel 3: finalize BN stats (double ~= exact) -------------
__global__ void k_stats() {
    __shared__ double sred[16][65];
    int tid = threadIdx.x;          // 1024 threads
    int col = tid & 63, seg = tid >> 6;
    if (tid == 0) g_fix_cnt = 0;
    double acc = 0.0;
    for (int p = seg; p < PP; p += 16)
        acc += g_part[p*64 + col];
    sred[seg][col] = acc;
    __syncthreads();
    if (tid < 64) {
        double s = 0.0;
#pragma unroll
        for (int i = 0; i < 16; i++) s += sred[i][tid];
        sred[0][tid] = s;
    }
    __syncthreads();
    if (tid < 32) {
        double sum   = sred[0][tid];
        double sumsq = sred[0][tid + 32];
        double mean_d = sum / 115200.0;
        float  mean_f = (float)mean_d;
        double var = sumsq / 115200.0
                   - 2.0 * (double)mean_f * mean_d
                   + (double)mean_f * (double)mean_f;
        float vf = (float)var;
        g_mean[tid] = mean_f;
        g_rstd[tid] = rsqrtf(__fadd_rn(vf, 1e-5f));
    }
}

// ---- elementwise core (reference op order, _rn to forbid fusion) ----------
__device__ __forceinline__ void lif_core(
    float alpha, float rho, float eta,
    float cv, float rec, float sv, float btv, float acv, float fbv, float somav,
    float mean, float rstd, float gm, float bt_,
    float& sn, float& spike, float& an, float& bn)
{
    bn = __fadd_rn(__fmul_rn(rho, btv), __fmul_rn(__fsub_rn(1.0f, rho), sv));
    float thr = __fadd_rn(0.1f, __fmul_rn(1.8f, bn));
    an = __fadd_rn(__fmul_rn(eta, acv), fbv);
    float sig = __fdiv_rn(1.0f, __fadd_rn(1.0f, expf(-an)));
    float xn = __fmul_rn(__fsub_rn(cv, mean), rstd);
    float cx = __fadd_rn(__fmul_rn(xn, gm), bt_);
    cx = __fadd_rn(cx, rec);
    float t  = __fadd_rn(__fmul_rn(alpha, somav), __fsub_rn(sig, 0.5f));
    t = __fadd_rn(t, cx);
    sn = __fsub_rn(t, __fmul_rn(thr, sv));
    spike = (__fsub_rn(sn, thr) > 0.0f) ? 1.0f : 0.0f;
}

// ---------------- kernel 4: fused BN-apply + LIF, float4 over p -------------
__global__ __launch_bounds__(256) void k_final(
    const float* __restrict__ fb, const float* __restrict__ soma,
    const float* __restrict__ spk, const float* __restrict__ ac,
    const float* __restrict__ bt,
    const float* __restrict__ gamma, const float* __restrict__ beta,
    float* __restrict__ out) {
    __shared__ float s_conv[64*61];          // [bol][pl], stride 61
    __shared__ float s_rec[64*61];
    __shared__ float s_mean[COUT], s_rstd[COUT], s_g[COUT], s_b[COUT];
    int bo0 = blockIdx.x * 64;               // 64 blocks
    int p0  = blockIdx.y * 60;               // 15 blocks
    int tid = threadIdx.x;
    if (tid < COUT) {
        s_mean[tid] = g_mean[tid];
        s_rstd[tid] = g_rstd[tid];
        s_g[tid]    = gamma[tid];
        s_b[tid]    = beta[tid];
    }
    const float4* gc4 = (const float4*)g_conv;
    const float4* gr4 = (const float4*)g_rec;
    for (int idx = tid; idx < 960; idx += 256) {
        int r = idx >> 4, c4 = idx & 15;
        size_t gsrc = ((size_t)(p0 + r)*BO + bo0)/4 + c4;
        float4 v = gc4[gsrc];
        float4 u = gr4[gsrc];
        int b0 = c4*4;
        s_conv[(b0  )*61 + r] = v.x; s_conv[(b0+1)*61 + r] = v.y;
        s_conv[(b0+2)*61 + r] = v.z; s_conv[(b0+3)*61 + r] = v.w;
        s_rec [(b0  )*61 + r] = u.x; s_rec [(b0+1)*61 + r] = u.y;
        s_rec [(b0+2)*61 + r] = u.z; s_rec [(b0+3)*61 + r] = u.w;
    }
    __syncthreads();
    for (int u = tid; u < 960; u += 256) {
        int bol = u / 15, pl = (u - bol*15)*4;
        int bo = bo0 + bol;
        int o = bo & 31;
        int gi = bo*PP + p0 + pl;
        int ti = o*PP + p0 + pl;
        float4 sv4 = *(const float4*)(spk + gi);
        float4 bt4 = *(const float4*)(bt + gi);
        float4 ac4 = *(const float4*)(ac + gi);
        float4 fb4 = *(const float4*)(fb + gi);
        float4 so4 = *(const float4*)(soma + gi);
        float4 al4 = *(const float4*)(g_alpha + ti);
        float4 rh4 = *(const float4*)(g_rho + ti);
        float4 et4 = *(const float4*)(g_eta + ti);
        float cvs[4], rcs[4];
#pragma unroll
        for (int i = 0; i < 4; i++) {
            cvs[i] = s_conv[bol*61 + pl + i];
            rcs[i] = s_rec [bol*61 + pl + i];
        }
        float mean = s_mean[o], rstd = s_rstd[o], gm = s_g[o], bb = s_b[o];
        float sn[4], spike[4], an[4], bn[4];
        const float* svp = &sv4.x; const float* btp = &bt4.x;
        const float* acp = &ac4.x; const float* fbp = &fb4.x;
        const float* sop = &so4.x; const float* alp = &al4.x;
        const float* rhp = &rh4.x; const float* etp = &et4.x;
#pragma unroll
        for (int i = 0; i < 4; i++) {
            lif_core(alp[i], rhp[i], etp[i],
                     cvs[i], rcs[i], svp[i], btp[i], acp[i], fbp[i], sop[i],
                     mean, rstd, gm, bb,
                     sn[i], spike[i], an[i], bn[i]);
        }
        *(float4*)(out + gi)           = make_float4(sn[0], sn[1], sn[2], sn[3]);
        *(float4*)(out + NELEM + gi)   = make_float4(spike[0], spike[1], spike[2], spike[3]);
        *(float4*)(out + 2*NELEM + gi) = make_float4(an[0], an[1], an[2], an[3]);
        *(float4*)(out + 3*NELEM + gi) = make_float4(bn[0], bn[1], bn[2], bn[3]);
#pragma unroll
        for (int i = 0; i < 4; i++) {
            float thr = __fadd_rn(0.1f, __fmul_rn(1.8f, bn[i]));
            if (fabsf(__fsub_rn(sn[i], thr)) < MARGIN_TAU) {
                int slot = atomicAdd(&g_fix_cnt, 1);
                if (slot < FIXCAP) g_fix_list[slot] = gi + i;
            }
        }
    }
}

// ---------------- kernel 5: exact f64 recompute of flagged elements ---------
__global__ __launch_bounds__(256) void k_fixup(
    const float* __restrict__ lr, const float* __restrict__ bias,
    const float* __restrict__ fb, const float* __restrict__ soma,
    const float* __restrict__ spk, const float* __restrict__ ac,
    const float* __restrict__ bt,
    const float* __restrict__ gamma, const float* __restrict__ beta,
    float* __restrict__ out) {
    int n = g_fix_cnt;
    if (n > FIXCAP) n = FIXCAP;
    int lane = threadIdx.x & 31;
    int wglob = (blockIdx.x * blockDim.x + threadIdx.x) >> 5;
    int nw = (gridDim.x * blockDim.x) >> 5;
    for (int e = wglob; e < n; e += nw) {
        int g = g_fix_list[e];
        int p  = g % PP;
        int bo = g / PP;
        int o = bo & 31, b = bo >> 5;
        int h = p / 30, w0 = p - h*30;
        double acc = 0.0;
        for (int k = lane; k < 144; k += 32) {
            int c = k / 9, r = k - c*9;
            int y = h + r/3, x = w0 + (r - (r/3)*3);
            double pv = (double)g_fft[(size_t)((c*32 + y)*32 + x)*128 + b];
            double wv = (double)g_wtt[((size_t)p*KC + k)*32 + o];
            acc = fma(pv, wv, acc);
        }
#pragma unroll
        for (int off = 16; off > 0; off >>= 1)
            acc += __shfl_xor_sync(0xffffffffu, acc, off);
        double lv = (double)lr[(size_t)p*1024 + o*32 + lane];
        double sj = (double)spk[((size_t)b*32 + lane)*PP + p];
        double racc = lv * sj;
#pragma unroll
        for (int off = 16; off > 0; off >>= 1)
            racc += __shfl_xor_sync(0xffffffffu, racc, off);
        if (lane == 0) {
            float cv  = __fadd_rn((float)acc, bias[o*PP + p]);
            float rec = (float)racc;
            int tix = o*PP + p;
            float sv = spk[g];
            float sn, spike, an, bn;
            lif_core(g_alpha[tix], g_rho[tix], g_eta[tix],
                     cv, rec, sv, bt[g], ac[g], fb[g], soma[g],
                     g_mean[o], g_rstd[o], gamma[o], beta[o],
                     sn, spike, an, bn);
            out[g]            = sn;
            out[NELEM + g]    = spike;
            out[2*NELEM + g]  = an;
            out[3*NELEM + g]  = bn;
        }
    }
}

// ---------------------------------------------------------------------------
extern "C" void kernel_launch(void* const* d_in, const int* in_sizes, int n_in,
                              void* d_out, int out_size) {
    const float* ff      = (const float*)d_in[0];
    const float* fb      = (const float*)d_in[1];
    const float* soma    = (const float*)d_in[2];
    const float* spk     = (const float*)d_in[3];
    const float* ac      = (const float*)d_in[4];
    const float* bt      = (const float*)d_in[5];
    const float* wt      = (const float*)d_in[6];
    const float* bias    = (const float*)d_in[7];
    const float* lr      = (const float*)d_in[8];
    const float* gamma   = (const float*)d_in[9];
    const float* beta    = (const float*)d_in[10];
    const float* tau_m   = (const float*)d_in[11];
    const float* tau_adp = (const float*)d_in[12];
    const float* tau_a   = (const float*)d_in[13];
    float* out = (float*)d_out;

    k_transpose_ff <<<dim3(512, 4),     dim3(32, 8)>>>(ff);
    k_transpose_spk<<<dim3(29, 4, 32),  dim3(32, 8)>>>(spk);
    k_transform_w  <<<dim3(57, 16),     256>>>(wt);

    const int smem2 = 41472;
    cudaFuncSetAttribute(k_conv_rec, cudaFuncAttributeMaxDynamicSharedMemorySize, smem2);
    k_conv_rec<<<900, 256, smem2>>>(lr, bias);      // 4th launch -> profiled

    k_taus <<<113, 256>>>(tau_m, tau_adp, tau_a);
    k_stats<<<1, 1024>>>();
    k_final<<<dim3(64, 15), 256>>>(fb, soma, spk, ac, bt, gamma, beta, out);
    k_fixup<<<148, 256>>>(lr, bias, fb, soma, spk, ac, bt, gamma, beta, out);
}

// round 15
// speedup vs baseline: 1.2181x; 1.2181x over previous
#include <cuda_runtime.h>

#define BB 128
#define CIN 16
#define COUT 32
#define HH 32
#define WW 32
#define HOUT 30
#define WOUT 30
#define PP 900
#define KC 144            // CIN * 9
#define NELEM (BB*COUT*PP)   // 3686400
#define BO 4096           // BB*COUT
#define FIXCAP (1<<20)
#define MARGIN_TAU 2e-3f

// ---------------- scratch (static __device__, no allocation) ----------------
__device__ float  g_fft[CIN*HH*WW*BB];   // [c][y][x][b]
__device__ float  g_spkt[PP*BO];         // [p][j][b]
__device__ float  g_wtt[PP*KC*COUT];     // [p][kc][o]
__device__ float  g_conv[PP*BO];         // [p][b*32+o]
__device__ float  g_rec[PP*BO];          // [p][b*32+o]
__device__ double g_part[PP*64];         // [p][ sum(32) | sumsq(32) ]
__device__ float  g_mean[COUT];
__device__ float  g_rstd[COUT];
__device__ float  g_alpha[COUT*PP];
__device__ float  g_rho[COUT*PP];
__device__ float  g_eta[COUT*PP];
__device__ int    g_fix_cnt;
__device__ int    g_fix_list[FIXCAP];

union F4U2 { float4 f4; unsigned long long u2[2]; float f[4]; };

__device__ __forceinline__ unsigned long long ffma2(
    unsigned long long a, unsigned long long b, unsigned long long c) {
    unsigned long long d;
    asm("fma.rn.f32x2 %0, %1, %2, %3;" : "=l"(d) : "l"(a), "l"(b), "l"(c));
    return d;
}

// ---------------- kernel 1 (fused prep): all 4 independent prep phases ------
// blocks [0,2048): transpose_ff   (512 x 4, tile 32x32)
// blocks [2048,5760): transpose_spk (29 x 4 x 32)
// blocks [5760,6672): transform_w (57 x 16)
// blocks [6672,6785): taus        (113)
__global__ __launch_bounds__(256) void k_prep(
    const float* __restrict__ ff, const float* __restrict__ spk,
    const float* __restrict__ wt,
    const float* __restrict__ tau_m, const float* __restrict__ tau_adp,
    const float* __restrict__ tau_a) {
    __shared__ float sbuf[32*145];          // max of 32x33 and 32x145
    int blk = blockIdx.x;
    int tid = threadIdx.x;

    if (blk < 2048) {
        // ---- transpose_ff: ff [128][16384] -> g_fft [16384][128] ----
        float (*t)[33] = (float(*)[33])sbuf;
        int bx = blk & 511, by = blk >> 9;
        int tx = tid & 31, ty = tid >> 5;   // ty 0..7
        int x  = bx*32 + tx;                // chw
        int y0 = by*32;                     // b
#pragma unroll
        for (int j = 0; j < 32; j += 8)
            t[ty+j][tx] = ff[(size_t)(y0+ty+j)*16384 + x];
        __syncthreads();
        int xo  = by*32 + tx;               // b
        int yo0 = bx*32;
#pragma unroll
        for (int j = 0; j < 32; j += 8)
            g_fft[(size_t)(yo0+ty+j)*128 + xo] = t[tx][ty+j];
    } else if (blk < 5760) {
        // ---- transpose_spk: spk [b][j][p] -> g_spkt [p][j][b] ----
        float (*t)[33] = (float(*)[33])sbuf;
        int idx = blk - 2048;
        int bx = idx % 29; idx /= 29;
        int by = idx & 3;
        int jz = idx >> 2;                  // 0..31
        int tx = tid & 31, ty = tid >> 5;
        int x  = bx*32 + tx;                // p
        int y0 = by*32;                     // b
#pragma unroll
        for (int j = 0; j < 32; j += 8) {
            int b = y0 + ty + j;
            if (x < PP)
                t[ty+j][tx] = spk[((size_t)b*32 + jz)*PP + x];
        }
        __syncthreads();
        int bo = by*32 + tx;                // b
#pragma unroll
        for (int j = 0; j < 32; j += 8) {
            int p = bx*32 + ty + j;
            if (p < PP)
                g_spkt[(size_t)p*BO + jz*128 + bo] = t[tx][ty+j];
        }
    } else if (blk < 6672) {
        // ---- transform_w: wt [o][c][p][k] -> g_wtt [p][c*9+k][o] ----
        float* s = sbuf;                    // [o][r], stride 145
        int idx = blk - 5760;
        int bx = idx % 57, c = idx / 57;
        int p0 = bx*16;
        int o = tid >> 3, lane = tid & 7;
        int rmax = (PP - p0)*9; if (rmax > 144) rmax = 144;
        const float* src = wt + (((size_t)o*CIN + c)*PP + p0)*9;
#pragma unroll
        for (int j = 0; j < 18; j++) {
            int r = lane + 8*j;
            if (r < rmax) s[o*145 + r] = src[r];
        }
        __syncthreads();
#pragma unroll
        for (int i = 0; i < 18; i++) {
            int e = tid + 256*i;            // 4608 = 16*9*32
            int o2 = e & 31, r = e >> 5;
            int pl = r / 9, k = r - pl*9;
            if (p0 + pl < PP)
                g_wtt[((size_t)(p0+pl)*KC + c*9 + k)*32 + o2] = s[o2*145 + r];
        }
    } else {
        // ---- taus: alpha/rho/eta per (o,p) ----
        int i = (blk - 6672)*256 + tid;
        if (i < COUT*PP) {
            g_alpha[i] = expf(__fdiv_rn(-0.5f, tau_m[i]));
            g_rho[i]   = expf(__fdiv_rn(-0.5f, tau_adp[i]));
            g_eta[i]   = expf(__fdiv_rn(-0.5f, tau_a[i]));
        }
    }
}

// ---------------- kernel 2: per-location conv + rec GEMMs (round-13 bytes) --
// o=8 per warp, k-half split; patch via LDG (compile-time offsets).
__global__ __launch_bounds__(256, 4) void k_conv_rec(
    const float* __restrict__ lr, const float* __restrict__ bias) {
    extern __shared__ float sm[];
    float4* sw4     = (float4*)sm;          // [k2*32+o] = (we,we,wo,wo), 2304
    float*  s_lr    = sm + 9216;            // [j*36 + o], 1152 floats
    float*  s_comb  = sm;                   // reuse: [e*256 + tid], 8192
    float*  s_stage = sm;                   // reuse: 4224 floats
    float4* sl4     = (float4*)s_lr;

    int p = blockIdx.x;
    int h = p / 30, w = p - h*30;
    int tid = threadIdx.x;
    int warp = tid >> 5, bi = tid & 31;
    int kh = warp & 1;                      // k-half
    int og = warp >> 1;                     // o octet (0..3)

    for (int idx = tid; idx < 2304; idx += 256) {
        int k2 = idx >> 5, o = idx & 31;
        float we = g_wtt[((size_t)p*KC + 2*k2    )*32 + o];
        float wo = g_wtt[((size_t)p*KC + 2*k2 + 1)*32 + o];
        sw4[idx] = make_float4(we, we, wo, wo);
    }
    for (int idx = tid; idx < 1024; idx += 256)
        s_lr[(idx & 31)*36 + (idx >> 5)] = lr[(size_t)p*1024 + idx];
    __syncthreads();

    const float4* pbase = ((const float4*)g_fft) + ((size_t)h*32 + w)*32 + bi
                          + (size_t)kh*8*32768;
    const float4* wbase = sw4 + kh*36*32 + og*8;
    unsigned long long acc2[8][2] = {};
#pragma unroll
    for (int i = 0; i < 36; i++) {
        const int ke = 2*i,   ko = ke + 1;
        const int ce = ke/9,  re = ke - ce*9, ye = re/3, xe = re - ye*3;
        const int co = ko/9,  ro = ko - co*9, yo = ro/3, xo = ro - yo*3;
        F4U2 pe, po;
        pe.f4 = __ldg(pbase + ce*32768 + ye*1024 + xe*32);
        po.f4 = __ldg(pbase + co*32768 + yo*1024 + xo*32);
#pragma unroll
        for (int j = 0; j < 8; j++) {
            F4U2 wv; wv.f4 = wbase[i*32 + j];
            acc2[j][0] = ffma2(pe.u2[0], wv.u2[0], acc2[j][0]);
            acc2[j][1] = ffma2(pe.u2[1], wv.u2[0], acc2[j][1]);
            acc2[j][0] = ffma2(po.u2[0], wv.u2[1], acc2[j][0]);
            acc2[j][1] = ffma2(po.u2[1], wv.u2[1], acc2[j][1]);
        }
    }
    __syncthreads();
    float own[8][4];
#pragma unroll
    for (int j = 0; j < 8; j++) {
        F4U2 u; u.u2[0] = acc2[j][0]; u.u2[1] = acc2[j][1];
#pragma unroll
        for (int i = 0; i < 4; i++) {
            own[j][i] = u.f[i];
            s_comb[(j*4 + i)*256 + tid] = u.f[i];
        }
    }
    __syncthreads();

    float acc[8][4];
    if (kh == 0) {
#pragma unroll
        for (int j = 0; j < 8; j++) {
            float bv = bias[(og*8 + j)*PP + p];
#pragma unroll
            for (int i = 0; i < 4; i++)
                acc[j][i] = __fadd_rn(
                    __fadd_rn(own[j][i], s_comb[(j*4 + i)*256 + tid + 32]), bv);
        }
        double ps[8], pq[8];
#pragma unroll
        for (int j = 0; j < 8; j++) {
            double a0 = acc[j][0], a1 = acc[j][1], a2 = acc[j][2], a3 = acc[j][3];
            ps[j] = (a0 + a1) + (a2 + a3);
            pq[j] = (a0*a0 + a1*a1) + (a2*a2 + a3*a3);
        }
#pragma unroll
        for (int off = 16; off > 0; off >>= 1) {
#pragma unroll
            for (int j = 0; j < 8; j++) {
                ps[j] += __shfl_down_sync(0xffffffffu, ps[j], off);
                pq[j] += __shfl_down_sync(0xffffffffu, pq[j], off);
            }
        }
        if (bi == 0) {
#pragma unroll
            for (int j = 0; j < 8; j++) {
                g_part[p*64 + og*8 + j]      = ps[j];
                g_part[p*64 + 32 + og*8 + j] = pq[j];
            }
        }
    }
    __syncthreads();
    if (kh == 0) {
#pragma unroll
        for (int i = 0; i < 4; i++)
#pragma unroll
            for (int j = 0; j < 8; j++)
                s_stage[(4*bi + i)*33 + og*8 + j] = acc[j][i];
    }
    __syncthreads();
    for (int idx = tid; idx < 4096; idx += 256)
        g_conv[(size_t)p*BO + idx] = s_stage[(idx >> 5)*33 + (idx & 31)];

    // ---- rec GEMM (f32, spk via LDG) ----
    int oi = warp;
    float racc[4][4];
#pragma unroll
    for (int j = 0; j < 4; j++)
#pragma unroll
        for (int i = 0; i < 4; i++) racc[j][i] = 0.f;
    const float4* skb = ((const float4*)g_spkt) + (size_t)p*1024 + bi;
#pragma unroll 8
    for (int jj = 0; jj < 32; jj++) {
        float4 pv = __ldg(skb + jj*32);
        float4 lv = sl4[jj*9 + oi];
        racc[0][0] += pv.x*lv.x; racc[0][1] += pv.y*lv.x; racc[0][2] += pv.z*lv.x; racc[0][3] += pv.w*lv.x;
        racc[1][0] += pv.x*lv.y; racc[1][1] += pv.y*lv.y; racc[1][2] += pv.z*lv.y; racc[1][3] += pv.w*lv.y;
        racc[2][0] += pv.x*lv.z; racc[2][1] += pv.y*lv.z; racc[2][2] += pv.z*lv.z; racc[2][3] += pv.w*lv.z;
        racc[3][0] += pv.x*lv.w; racc[3][1] += pv.y*lv.w; racc[3][2] += pv.z*lv.w; racc[3][3] += pv.w*lv.w;
    }
    __syncthreads();
#pragma unroll
    for (int i = 0; i < 4; i++)
#pragma unroll
        for (int j = 0; j < 4; j++)
            s_stage[(4*bi + i)*33 + 4*oi + j] = racc[j][i];
    __syncthreads();
    for (int idx = tid; idx < 4096; idx += 256)
        g_rec[(size_t)p*BO + idx] = s_stage[(idx >> 5)*33 + (idx & 31)];
}

// ---------------- kernel 3: finalize BN stats (double ~= exact) -------------
__global__ void k_stats() {
    __shared__ double sred[16][65];
    int tid = threadIdx.x;          // 1024 threads
    int col = tid & 63, seg = tid >> 6;
    if (tid == 0) g_fix_cnt = 0;
    double acc = 0.0;
    for (int p = seg; p < PP; p += 16)
        acc += g_part[p*64 + col];
    sred[seg][col] = acc;
    __syncthreads();
    if (tid < 64) {
        double s = 0.0;
#pragma unroll
        for (int i = 0; i < 16; i++) s += sred[i][tid];
        sred[0][tid] = s;
    }
    __syncthreads();
    if (tid < 32) {
        double sum   = sred[0][tid];
        double sumsq = sred[0][tid + 32];
        double mean_d = sum / 115200.0;
        float  mean_f = (float)mean_d;
        double var = sumsq / 115200.0
                   - 2.0 * (double)mean_f * mean_d
                   + (double)mean_f * (double)mean_f;
        float vf = (float)var;
        g_mean[tid] = mean_f;
        g_rstd[tid] = rsqrtf(__fadd_rn(vf, 1e-5f));
    }
}

// ---- elementwise core (reference op order, _rn to forbid fusion) ----------
__device__ __forceinline__ void lif_core(
    float alpha, float rho, float eta,
    float cv, float rec, float sv, float btv, float acv, float fbv, float somav,
    float mean, float rstd, float gm, float bt_,
    float& sn, float& spike, float& an, float& bn)
{
    bn = __fadd_rn(__fmul_rn(rho, btv), __fmul_rn(__fsub_rn(1.0f, rho), sv));
    float thr = __fadd_rn(0.1f, __fmul_rn(1.8f, bn));
    an = __fadd_rn(__fmul_rn(eta, acv), fbv);
    float sig = __fdiv_rn(1.0f, __fadd_rn(1.0f, expf(-an)));
    float xn = __fmul_rn(__fsub_rn(cv, mean), rstd);
    float cx = __fadd_rn(__fmul_rn(xn, gm), bt_);
    cx = __fadd_rn(cx, rec);
    float t  = __fadd_rn(__fmul_rn(alpha, somav), __fsub_rn(sig, 0.5f));
    t = __fadd_rn(t, cx);
    sn = __fsub_rn(t, __fmul_rn(thr, sv));
    spike = (__fsub_rn(sn, thr) > 0.0f) ? 1.0f : 0.0f;
}

// ---------------- kernel 4: fused BN-apply + LIF, float4 over p -------------
__global__ __launch_bounds__(256) void k_final(
    const float* __restrict__ fb, const float* __restrict__ soma,
    const float* __restrict__ spk, const float* __restrict__ ac,
    const float* __restrict__ bt,
    const float* __restrict__ gamma, const float* __restrict__ beta,
    float* __restrict__ out) {
    __shared__ float s_conv[64*61];          // [bol][pl], stride 61
    __shared__ float s_rec[64*61];
    __shared__ float s_mean[COUT], s_rstd[COUT], s_g[COUT], s_b[COUT];
    int bo0 = blockIdx.x * 64;               // 64 blocks
    int p0  = blockIdx.y * 60;               // 15 blocks
    int tid = threadIdx.x;
    if (tid < COUT) {
        s_mean[tid] = g_mean[tid];
        s_rstd[tid] = g_rstd[tid];
        s_g[tid]    = gamma[tid];
        s_b[tid]    = beta[tid];
    }
    const float4* gc4 = (const float4*)g_conv;
    const float4* gr4 = (const float4*)g_rec;
    for (int idx = tid; idx < 960; idx += 256) {
        int r = idx >> 4, c4 = idx & 15;
        size_t gsrc = ((size_t)(p0 + r)*BO + bo0)/4 + c4;
        float4 v = gc4[gsrc];
        float4 u = gr4[gsrc];
        int b0 = c4*4;
        s_conv[(b0  )*61 + r] = v.x; s_conv[(b0+1)*61 + r] = v.y;
        s_conv[(b0+2)*61 + r] = v.z; s_conv[(b0+3)*61 + r] = v.w;
        s_rec [(b0  )*61 + r] = u.x; s_rec [(b0+1)*61 + r] = u.y;
        s_rec [(b0+2)*61 + r] = u.z; s_rec [(b0+3)*61 + r] = u.w;
    }
    __syncthreads();
    for (int u = tid; u < 960; u += 256) {
        int bol = u / 15, pl = (u - bol*15)*4;
        int bo = bo0 + bol;
        int o = bo & 31;
        int gi = bo*PP + p0 + pl;
        int ti = o*PP + p0 + pl;
        float4 sv4 = *(const float4*)(spk + gi);
        float4 bt4 = *(const float4*)(bt + gi);
        float4 ac4 = *(const float4*)(ac + gi);
        float4 fb4 = *(const float4*)(fb + gi);
        float4 so4 = *(const float4*)(soma + gi);
        float4 al4 = *(const float4*)(g_alpha + ti);
        float4 rh4 = *(const float4*)(g_rho + ti);
        float4 et4 = *(const float4*)(g_eta + ti);
        float cvs[4], rcs[4];
#pragma unroll
        for (int i = 0; i < 4; i++) {
            cvs[i] = s_conv[bol*61 + pl + i];
            rcs[i] = s_rec [bol*61 + pl + i];
        }
        float mean = s_mean[o], rstd = s_rstd[o], gm = s_g[o], bb = s_b[o];
        float sn[4], spike[4], an[4], bn[4];
        const float* svp = &sv4.x; const float* btp = &bt4.x;
        const float* acp = &ac4.x; const float* fbp = &fb4.x;
        const float* sop = &so4.x; const float* alp = &al4.x;
        const float* rhp = &rh4.x; const float* etp = &et4.x;
#pragma unroll
        for (int i = 0; i < 4; i++) {
            lif_core(alp[i], rhp[i], etp[i],
                     cvs[i], rcs[i], svp[i], btp[i], acp[i], fbp[i], sop[i],
                     mean, rstd, gm, bb,
                     sn[i], spike[i], an[i], bn[i]);
        }
        *(float4*)(out + gi)           = make_float4(sn[0], sn[1], sn[2], sn[3]);
        *(float4*)(out + NELEM + gi)   = make_float4(spike[0], spike[1], spike[2], spike[3]);
        *(float4*)(out + 2*NELEM + gi) = make_float4(an[0], an[1], an[2], an[3]);
        *(float4*)(out + 3*NELEM + gi) = make_float4(bn[0], bn[1], bn[2], bn[3]);
#pragma unroll
        for (int i = 0; i < 4; i++) {
            float thr = __fadd_rn(0.1f, __fmul_rn(1.8f, bn[i]));
            if (fabsf(__fsub_rn(sn[i], thr)) < MARGIN_TAU) {
                int slot = atomicAdd(&g_fix_cnt, 1);
                if (slot < FIXCAP) g_fix_list[slot] = gi + i;
            }
        }
    }
}

// ---------------- kernel 5: exact f64 recompute of flagged elements ---------
__global__ __launch_bounds__(256) void k_fixup(
    const float* __restrict__ lr, const float* __restrict__ bias,
    const float* __restrict__ fb, const float* __restrict__ soma,
    const float* __restrict__ spk, const float* __restrict__ ac,
    const float* __restrict__ bt,
    const float* __restrict__ gamma, const float* __restrict__ beta,
    float* __restrict__ out) {
    int n = g_fix_cnt;
    if (n > FIXCAP) n = FIXCAP;
    int lane = threadIdx.x & 31;
    int wglob = (blockIdx.x * blockDim.x + threadIdx.x) >> 5;
    int nw = (gridDim.x * blockDim.x) >> 5;
    for (int e = wglob; e < n; e += nw) {
        int g = g_fix_list[e];
        int p  = g % PP;
        int bo = g / PP;
        int o = bo & 31, b = bo >> 5;
        int h = p / 30, w0 = p - h*30;
        double acc = 0.0;
        for (int k = lane; k < 144; k += 32) {
            int c = k / 9, r = k - c*9;
            int y = h + r/3, x = w0 + (r - (r/3)*3);
            double pv = (double)g_fft[(size_t)((c*32 + y)*32 + x)*128 + b];
            double wv = (double)g_wtt[((size_t)p*KC + k)*32 + o];
            acc = fma(pv, wv, acc);
        }
#pragma unroll
        for (int off = 16; off > 0; off >>= 1)
            acc += __shfl_xor_sync(0xffffffffu, acc, off);
        double lv = (double)lr[(size_t)p*1024 + o*32 + lane];
        double sj = (double)spk[((size_t)b*32 + lane)*PP + p];
        double racc = lv * sj;
#pragma unroll
        for (int off = 16; off > 0; off >>= 1)
            racc += __shfl_xor_sync(0xffffffffu, racc, off);
        if (lane == 0) {
            float cv  = __fadd_rn((float)acc, bias[o*PP + p]);
            float rec = (float)racc;
            int tix = o*PP + p;
            float sv = spk[g];
            float sn, spike, an, bn;
            lif_core(g_alpha[tix], g_rho[tix], g_eta[tix],
                     cv, rec, sv, bt[g], ac[g], fb[g], soma[g],
                     g_mean[o], g_rstd[o], gamma[o], beta[o],
                     sn, spike, an, bn);
            out[g]            = sn;
            out[NELEM + g]    = spike;
            out[2*NELEM + g]  = an;
            out[3*NELEM + g]  = bn;
        }
    }
}

// ---------------------------------------------------------------------------
extern "C" void kernel_launch(void* const* d_in, const int* in_sizes, int n_in,
                              void* d_out, int out_size) {
    const float* ff      = (const float*)d_in[0];
    const float* fb      = (const float*)d_in[1];
    const float* soma    = (const float*)d_in[2];
    const float* spk     = (const float*)d_in[3];
    const float* ac      = (const float*)d_in[4];
    const float* bt      = (const float*)d_in[5];
    const float* wt      = (const float*)d_in[6];
    const float* bias    = (const float*)d_in[7];
    const float* lr      = (const float*)d_in[8];
    const float* gamma   = (const float*)d_in[9];
    const float* beta    = (const float*)d_in[10];
    const float* tau_m   = (const float*)d_in[11];
    const float* tau_adp = (const float*)d_in[12];
    const float* tau_a   = (const float*)d_in[13];
    float* out = (float*)d_out;

    k_prep<<<6785, 256>>>(ff, spk, wt, tau_m, tau_adp, tau_a);

    const int smem2 = 41472;
    cudaFuncSetAttribute(k_conv_rec, cudaFuncAttributeMaxDynamicSharedMemorySize, smem2);
    k_conv_rec<<<900, 256, smem2>>>(lr, bias);

    k_stats<<<1, 1024>>>();
    k_final<<<dim3(64, 15), 256>>>(fb, soma, spk, ac, bt, gamma, beta, out);
    k_fixup<<<148, 256>>>(lr, bias, fb, soma, spk, ac, bt, gamma, beta, out);
}